// round 10
// baseline (speedup 1.0000x reference)
#include <cuda_runtime.h>
#include <cuda_bf16.h>
#include <cstdint>

// ---------------- problem constants ----------------
#define Bb 4
#define Ss 2048
#define Ee 768
#define Hh 3
#define Dd 256
#define BHh 12
#define SCALE 0.022097086912079608f   // 1/sqrt(2048)

#define NE (8192 * 768)
#define EE (768 * 768)

// ---------------- scratch (device globals; no cudaMalloc allowed) ----------------
__device__ __align__(16) __nv_bfloat16 g_Xhi[3][NE];
__device__ __align__(16) __nv_bfloat16 g_Xlo[3][NE];
__device__ __align__(16) __nv_bfloat16 g_Wthi[3][EE];   // W^T: [n=h*256+d][k=e]
__device__ __align__(16) __nv_bfloat16 g_Wtlo[3][EE];
__device__ __align__(16) __nv_bfloat16 g_Wohi[EE];      // Wo^T: [n=eout][k=ein]
__device__ __align__(16) __nv_bfloat16 g_Wolo[EE];
__device__ __align__(16) __nv_bfloat16 g_Qhi[BHh * Ss * Dd];  // [z][s][d]
__device__ __align__(16) __nv_bfloat16 g_Qlo[BHh * Ss * Dd];
__device__ __align__(16) __nv_bfloat16 g_Khi[BHh * Ss * Dd];
__device__ __align__(16) __nv_bfloat16 g_Klo[BHh * Ss * Dd];
__device__ __align__(16) __nv_bfloat16 g_Vthi[BHh * Dd * Ss]; // [z][d][s]
__device__ __align__(16) __nv_bfloat16 g_Vtlo[BHh * Dd * Ss];
__device__ __align__(16) __nv_bfloat16 g_Chi[NE];
__device__ __align__(16) __nv_bfloat16 g_Clo[NE];

// ---------------- helpers ----------------
__device__ __forceinline__ uint32_t smem_u32(const void* p) {
    uint32_t a;
    asm("{ .reg .u64 t; cvta.to.shared.u64 t, %1; cvt.u32.u64 %0, t; }" : "=r"(a) : "l"(p));
    return a;
}
__device__ __forceinline__ void ldsm4(uint32_t r[4], uint32_t addr) {
    asm volatile("ldmatrix.sync.aligned.m8n8.x4.shared.b16 {%0,%1,%2,%3}, [%4];"
                 : "=r"(r[0]), "=r"(r[1]), "=r"(r[2]), "=r"(r[3]) : "r"(addr));
}
__device__ __forceinline__ void mma16816(float c[4], const uint32_t a[4], uint32_t b0, uint32_t b1) {
    asm volatile("mma.sync.aligned.m16n8k16.row.col.f32.bf16.bf16.f32 "
                 "{%0,%1,%2,%3}, {%4,%5,%6,%7}, {%8,%9}, {%0,%1,%2,%3};"
                 : "+f"(c[0]), "+f"(c[1]), "+f"(c[2]), "+f"(c[3])
                 : "r"(a[0]), "r"(a[1]), "r"(a[2]), "r"(a[3]), "r"(b0), "r"(b1));
}
__device__ __forceinline__ void split2(float x, __nv_bfloat16& hi, __nv_bfloat16& lo) {
    hi = __float2bfloat16(x);
    lo = __float2bfloat16(x - __bfloat162float(hi));
}
__device__ __forceinline__ void cpa16(uint32_t dst, const void* src) {
    asm volatile("cp.async.cg.shared.global [%0], [%1], 16;" :: "r"(dst), "l"(src));
}

// ---------------- conversion kernels ----------------
__global__ __launch_bounds__(256) void conv_inputs(const float* __restrict__ Xk,
                                                   const float* __restrict__ Xv,
                                                   const float* __restrict__ Xq) {
    int i = blockIdx.x * blockDim.x + threadIdx.x;
    if (i >= NE) return;
    __nv_bfloat16 hi, lo;
    split2(Xk[i], hi, lo); g_Xhi[0][i] = hi; g_Xlo[0][i] = lo;
    split2(Xv[i], hi, lo); g_Xhi[1][i] = hi; g_Xlo[1][i] = lo;
    split2(Xq[i], hi, lo); g_Xhi[2][i] = hi; g_Xlo[2][i] = lo;
}

__global__ __launch_bounds__(256) void conv_weights(const float* __restrict__ WK,
                                                    const float* __restrict__ WV,
                                                    const float* __restrict__ WQ,
                                                    const float* __restrict__ Wo) {
    int i = blockIdx.x * blockDim.x + threadIdx.x;
    if (i >= EE) return;
    int h = i / (Ee * Dd);
    int r = i % (Ee * Dd);
    int e = r / Dd;
    int d = r % Dd;
    int dst = (h * Dd + d) * Ee + e;
    __nv_bfloat16 hi, lo;
    split2(WK[i], hi, lo); g_Wthi[0][dst] = hi; g_Wtlo[0][dst] = lo;
    split2(WV[i], hi, lo); g_Wthi[1][dst] = hi; g_Wtlo[1][dst] = lo;
    split2(WQ[i], hi, lo); g_Wthi[2][dst] = hi; g_Wtlo[2][dst] = lo;
    int k = i / Ee, n = i % Ee;
    split2(Wo[i], hi, lo); g_Wohi[n * Ee + k] = hi; g_Wolo[n * Ee + k] = lo;
}

// ---------------- mma.sync GEMM core: BK=64, 2-stage dynamic-smem pipeline (proven) ----
struct Seg { const __nv_bfloat16* A; const __nv_bfloat16* B; int klen; };

#define ROWB 144
#define HALF_STAGE (128 * ROWB)          // 18432
#define STAGE_BYTES (2 * HALF_STAGE)     // 36864
#define SMEM_TOTAL (2 * STAGE_BYTES)     // 73728

__device__ __forceinline__ void load_tiles(uint32_t st,
                                           const __nv_bfloat16* __restrict__ A, int lda,
                                           const __nv_bfloat16* __restrict__ B, int ldb,
                                           int k0) {
    int tid = threadIdx.x;
#pragma unroll
    for (int c = 0; c < 4; c++) {
        int idx = tid + c * 256;
        int row = idx >> 3, ch = idx & 7;
        cpa16(st + row * ROWB + ch * 16, A + (size_t)row * lda + k0 + ch * 8);
    }
#pragma unroll
    for (int c = 0; c < 4; c++) {
        int idx = tid + c * 256;
        int row = idx >> 3, ch = idx & 7;
        cpa16(st + HALF_STAGE + row * ROWB + ch * 16, B + (size_t)row * ldb + k0 + ch * 8);
    }
    asm volatile("cp.async.commit_group;");
}

__device__ __forceinline__ void compute_stage(uint32_t st, float acc[4][4][4],
                                              int wm, int wn, int lane) {
    uint32_t sA = st, sB = st + HALF_STAGE;
#pragma unroll
    for (int ks = 0; ks < 4; ks++) {
        uint32_t a[4][4];
#pragma unroll
        for (int mi = 0; mi < 4; mi++) {
            uint32_t addr = sA + (wm + mi * 16 + (lane & 15)) * ROWB + ks * 32 + (lane >> 4) * 16;
            ldsm4(a[mi], addr);
        }
        uint32_t b[2][4];
#pragma unroll
        for (int nj = 0; nj < 2; nj++) {
            uint32_t addr = sB + (wn + nj * 16 + (lane & 7) + ((lane >> 4) & 1) * 8) * ROWB +
                            ks * 32 + ((lane >> 3) & 1) * 16;
            ldsm4(b[nj], addr);
        }
#pragma unroll
        for (int mi = 0; mi < 4; mi++)
#pragma unroll
            for (int ni = 0; ni < 4; ni++)
                mma16816(acc[mi][ni], a[mi], b[ni >> 1][(ni & 1) * 2], b[ni >> 1][(ni & 1) * 2 + 1]);
    }
}

__device__ __forceinline__ void gemm_run(const Seg seg[3], int lda, int ldb,
                                         uint32_t sbase, float acc[4][4][4],
                                         int wm, int wn, int lane) {
    int total = (seg[0].klen + seg[1].klen + seg[2].klen) >> 6;
    int si = 0, k = 0;
    load_tiles(sbase, seg[0].A, lda, seg[0].B, ldb, 0);
    k = 64;
    if (k >= seg[0].klen) { k = 0; si = 1; }
    for (int t = 0; t < total; t++) {
        uint32_t cur = sbase + (t & 1) * STAGE_BYTES;
        if (t + 1 < total) {
            uint32_t nxt = sbase + ((t + 1) & 1) * STAGE_BYTES;
            load_tiles(nxt, seg[si].A, lda, seg[si].B, ldb, k);
            k += 64;
            if (k >= seg[si].klen) { k = 0; si++; }
            asm volatile("cp.async.wait_group 1;");
        } else {
            asm volatile("cp.async.wait_group 0;");
        }
        __syncthreads();
        compute_stage(cur, acc, wm, wn, lane);
        __syncthreads();
    }
}

// ---------------- projections (all 3 fused: blockIdx.z = m) ----------------
__global__ __launch_bounds__(256, 2) void mma_proj() {
    extern __shared__ __align__(16) char smd[];
    int m = blockIdx.z;
    int tid = threadIdx.x, lane = tid & 31, w = tid >> 5;
    int wm = (w & 1) * 64, wn = (w >> 1) * 32;
    uint32_t sbase = smem_u32(smd);
    int rowBase = blockIdx.y * 128, colBase = blockIdx.x * 128;
    float acc[4][4][4] = {};
    Seg seg[3] = {
        { g_Xhi[m] + (size_t)rowBase * Ee, g_Wthi[m] + (size_t)colBase * Ee, Ee },
        { g_Xlo[m] + (size_t)rowBase * Ee, g_Wthi[m] + (size_t)colBase * Ee, Ee },
        { g_Xhi[m] + (size_t)rowBase * Ee, g_Wtlo[m] + (size_t)colBase * Ee, Ee } };
    gemm_run(seg, Ee, Ee, sbase, acc, wm, wn, lane);

    int lr = lane >> 2, lc = (lane & 3) * 2;
#pragma unroll
    for (int mi = 0; mi < 4; mi++)
#pragma unroll
        for (int ni = 0; ni < 4; ni++)
#pragma unroll
            for (int half = 0; half < 2; half++) {
                int gr = rowBase + wm + mi * 16 + lr + half * 8;
                int b = gr >> 11, sI = gr & 2047;
                int col = colBase + wn + ni * 8 + lc;
                int h = col >> 8, d = col & 255;
                int z = b * Hh + h;
                float v0 = acc[mi][ni][half * 2], v1 = acc[mi][ni][half * 2 + 1];
                __nv_bfloat16 h0, l0, h1, l1;
                split2(v0, h0, l0);
                split2(v1, h1, l1);
                if (m == 1) {
                    size_t d0 = ((size_t)z * Dd + d) * Ss + sI;
                    size_t d1 = ((size_t)z * Dd + d + 1) * Ss + sI;
                    g_Vthi[d0] = h0; g_Vtlo[d0] = l0;
                    g_Vthi[d1] = h1; g_Vtlo[d1] = l1;
                } else {
                    size_t dst = ((size_t)z * Ss + sI) * Dd + d;
                    if (m == 0) { g_Khi[dst] = h0; g_Klo[dst] = l0;
                                  g_Khi[dst + 1] = h1; g_Klo[dst + 1] = l1; }
                    else        { g_Qhi[dst] = h0; g_Qlo[dst] = l0;
                                  g_Qhi[dst + 1] = h1; g_Qlo[dst + 1] = l1; }
                }
            }
}

// ---------------- flash attention: scores + softmax + PV fused ----------------
// Per CTA: z, 64-query row block. 512 threads = 16 warps (wy in {0,1} x wx in {0..7}).
// QK warp tile 32x16 (S = 64x128); PV warp tile 32x32 (O = 64x256).
#define FL_THREADS 512
#define QROWB 528                 // 256 d * 2B + 16 pad
#define PROWB 272                 // 128 k * 2B + 16 pad
#define SLOT  36864               // max stream chunk: V 256x144
#define OFF_QH 0
#define OFF_QL 33792
#define OFF_PH 67584
#define OFF_PL 84992
#define OFF_STREAM 102400
#define OFF_REDM 176128
#define OFF_REDS 178176
#define OFF_M 180224
#define OFF_L 180480
#define OFF_SC 180736
#define FL_SMEM 180992

__global__ void __launch_bounds__(FL_THREADS, 1) flash_attn() {
    extern __shared__ __align__(16) char smd[];
    uint32_t sb = smem_u32(smd);
    float* redM = (float*)(smd + OFF_REDM);
    float* redS = (float*)(smd + OFF_REDS);
    float* m_sm = (float*)(smd + OFF_M);
    float* l_sm = (float*)(smd + OFF_L);
    float* sc_sm = (float*)(smd + OFF_SC);

    int cid = blockIdx.x;
    int by = 31 - cid / 12;        // heavy tiles first
    int z = cid % 12;
    int rb = by * 64;
    int T = by / 2 + 1;            // number of 128-key tiles (incl. diagonal)

    int tid = threadIdx.x, lane = tid & 31, w = tid >> 5;
    int wy = w >> 3, wx = w & 7;
    int lr = lane >> 2, lc = (lane & 3) * 2;

    if (tid < 64) { m_sm[tid] = -1e30f; l_sm[tid] = 0.0f; }

    // load Q block (64 x 256, hi+lo) into smem
    {
        const __nv_bfloat16* srcs[2] = { g_Qhi + (size_t)z * Ss * Dd + (size_t)rb * Dd,
                                         g_Qlo + (size_t)z * Ss * Dd + (size_t)rb * Dd };
        uint32_t dsts[2] = { sb + OFF_QH, sb + OFF_QL };
#pragma unroll
        for (int p = 0; p < 2; p++)
#pragma unroll
            for (int it = 0; it < 4; it++) {
                int idx = tid + it * 512;
                int row = idx >> 5, ch = idx & 31;
                cpa16(dsts[p] + row * QROWB + ch * 16, srcs[p] + (size_t)row * Dd + ch * 8);
            }
        asm volatile("cp.async.commit_group;");
    }

    float O[2][4][4] = {};
    size_t kvo = (size_t)z * Ss * Dd;
    size_t vvo = (size_t)z * Dd * Ss;

    for (int bx = 0; bx < T; bx++) {
        int kb = bx * 128;

        // ---- QK: 8 stream units. unit j<4: Kh d-chunk j*64 (passes Qh,Ql); j>=4: Kl chunk (Qh)
        {   // issue unit 0 into slot 0
            const __nv_bfloat16* base = g_Khi + kvo + (size_t)kb * Dd;
#pragma unroll
            for (int it = 0; it < 2; it++) {
                int idx = tid + it * 512;
                int row = idx >> 3, ch = idx & 7;
                cpa16(sb + OFF_STREAM + row * ROWB + ch * 16, base + (size_t)row * Dd + ch * 8);
            }
            asm volatile("cp.async.commit_group;");
        }
        float s[2][2][4] = {};
        for (int j = 0; j < 8; j++) {
            if (j < 7) {
                int jn = j + 1;
                int dj = (jn < 4 ? jn : jn - 4) * 64;
                const __nv_bfloat16* plane = (jn < 4) ? g_Khi : g_Klo;
                const __nv_bfloat16* base = plane + kvo + (size_t)kb * Dd + dj;
                uint32_t st = sb + OFF_STREAM + (jn & 1) * SLOT;
#pragma unroll
                for (int it = 0; it < 2; it++) {
                    int idx = tid + it * 512;
                    int row = idx >> 3, ch = idx & 7;
                    cpa16(st + row * ROWB + ch * 16, base + (size_t)row * Dd + ch * 8);
                }
                asm volatile("cp.async.commit_group;");
                asm volatile("cp.async.wait_group 1;");
            } else {
                asm volatile("cp.async.wait_group 0;");
            }
            __syncthreads();
            uint32_t bbase = sb + OFF_STREAM + (j & 1) * SLOT;
            int dj = (j < 4 ? j : j - 4) * 64;
            int np = (j < 4) ? 2 : 1;
            for (int p = 0; p < np; p++) {
                uint32_t abase = sb + ((j < 4 && p == 1) ? OFF_QL : OFF_QH) + dj * 2;
#pragma unroll
                for (int ks = 0; ks < 4; ks++) {
                    uint32_t a[2][4];
#pragma unroll
                    for (int mf = 0; mf < 2; mf++)
                        ldsm4(a[mf], abase + (wy * 32 + mf * 16 + (lane & 15)) * QROWB +
                                     ks * 32 + (lane >> 4) * 16);
                    uint32_t b[4];
                    ldsm4(b, bbase + (wx * 16 + (lane & 7) + ((lane >> 4) & 1) * 8) * ROWB +
                             ks * 32 + ((lane >> 3) & 1) * 16);
#pragma unroll
                    for (int mf = 0; mf < 2; mf++) {
                        mma16816(s[mf][0], a[mf], b[0], b[1]);
                        mma16816(s[mf][1], a[mf], b[2], b[3]);
                    }
                }
            }
            __syncthreads();
        }

        // ---- scale + causal mask (last tile only)
#pragma unroll
        for (int mf = 0; mf < 2; mf++)
#pragma unroll
            for (int ni = 0; ni < 2; ni++)
#pragma unroll
                for (int c = 0; c < 4; c++)
                    s[mf][ni][c] *= SCALE;
        if (bx == T - 1) {
            int lim = rb - kb;   // mask where col - row > lim
#pragma unroll
            for (int mf = 0; mf < 2; mf++)
#pragma unroll
                for (int ni = 0; ni < 2; ni++)
#pragma unroll
                    for (int c = 0; c < 4; c++) {
                        int row = wy * 32 + mf * 16 + lr + ((c >> 1) << 3);
                        int col = wx * 16 + ni * 8 + lc + (c & 1);
                        if (col - row > lim) s[mf][ni][c] = -1e30f;
                    }
        }

        // ---- row max: per-lane partial -> quad shuffle -> smem
        float pm[2][2];
#pragma unroll
        for (int mf = 0; mf < 2; mf++) {
            pm[mf][0] = fmaxf(fmaxf(s[mf][0][0], s[mf][0][1]), fmaxf(s[mf][1][0], s[mf][1][1]));
            pm[mf][1] = fmaxf(fmaxf(s[mf][0][2], s[mf][0][3]), fmaxf(s[mf][1][2], s[mf][1][3]));
#pragma unroll
            for (int h2 = 0; h2 < 2; h2++) {
                float v = pm[mf][h2];
                v = fmaxf(v, __shfl_xor_sync(0xffffffffu, v, 1));
                v = fmaxf(v, __shfl_xor_sync(0xffffffffu, v, 2));
                pm[mf][h2] = v;
            }
            if ((lane & 3) == 0) {
                redM[wx * 64 + wy * 32 + mf * 16 + lr] = pm[mf][0];
                redM[wx * 64 + wy * 32 + mf * 16 + lr + 8] = pm[mf][1];
            }
        }
        __syncthreads();
        if (tid < 64) {
            float tm = redM[tid];
#pragma unroll
            for (int x2 = 1; x2 < 8; x2++) tm = fmaxf(tm, redM[x2 * 64 + tid]);
            float mo = m_sm[tid];
            float mn = fmaxf(mo, tm);
            sc_sm[tid] = __expf(mo - mn);
            m_sm[tid] = mn;
        }
        __syncthreads();

        // ---- O rescale, exp, P write (hi/lo), partial row sums
        float ps[2][2] = {};
#pragma unroll
        for (int mf = 0; mf < 2; mf++) {
            int r0 = wy * 32 + mf * 16 + lr, r1 = r0 + 8;
            float mn0 = m_sm[r0], mn1 = m_sm[r1];
            float sc0 = sc_sm[r0], sc1 = sc_sm[r1];
#pragma unroll
            for (int ni = 0; ni < 4; ni++) {
                O[mf][ni][0] *= sc0; O[mf][ni][1] *= sc0;
                O[mf][ni][2] *= sc1; O[mf][ni][3] *= sc1;
            }
#pragma unroll
            for (int ni = 0; ni < 2; ni++) {
                float e0 = __expf(s[mf][ni][0] - mn0), e1 = __expf(s[mf][ni][1] - mn0);
                float e2 = __expf(s[mf][ni][2] - mn1), e3 = __expf(s[mf][ni][3] - mn1);
                ps[mf][0] += e0 + e1;
                ps[mf][1] += e2 + e3;
                int colb = (wx * 16 + ni * 8 + lc) * 2;
                __nv_bfloat16 h0, l0, h1, l1;
                split2(e0, h0, l0); split2(e1, h1, l1);
                *(uint32_t*)(smd + OFF_PH + r0 * PROWB + colb) =
                    (uint32_t)*(uint16_t*)&h0 | ((uint32_t)*(uint16_t*)&h1 << 16);
                *(uint32_t*)(smd + OFF_PL + r0 * PROWB + colb) =
                    (uint32_t)*(uint16_t*)&l0 | ((uint32_t)*(uint16_t*)&l1 << 16);
                split2(e2, h0, l0); split2(e3, h1, l1);
                *(uint32_t*)(smd + OFF_PH + r1 * PROWB + colb) =
                    (uint32_t)*(uint16_t*)&h0 | ((uint32_t)*(uint16_t*)&h1 << 16);
                *(uint32_t*)(smd + OFF_PL + r1 * PROWB + colb) =
                    (uint32_t)*(uint16_t*)&l0 | ((uint32_t)*(uint16_t*)&l1 << 16);
            }
#pragma unroll
            for (int h2 = 0; h2 < 2; h2++) {
                float v = ps[mf][h2];
                v += __shfl_xor_sync(0xffffffffu, v, 1);
                v += __shfl_xor_sync(0xffffffffu, v, 2);
                ps[mf][h2] = v;
            }
            if ((lane & 3) == 0) {
                redS[wx * 64 + wy * 32 + mf * 16 + lr] = pm[mf][0] = ps[mf][0];
                redS[wx * 64 + wy * 32 + mf * 16 + lr + 8] = ps[mf][1];
            }
        }

        // issue V unit 0 (slot 0) now — overlaps softmax tail
        {
            const __nv_bfloat16* base = g_Vthi + vvo + kb;
#pragma unroll
            for (int it = 0; it < 4; it++) {
                int idx = tid + it * 512;
                int row = idx >> 3, ch = idx & 7;
                cpa16(sb + OFF_STREAM + row * ROWB + ch * 16, base + (size_t)row * Ss + ch * 8);
            }
            asm volatile("cp.async.commit_group;");
        }
        __syncthreads();   // P + redS visible
        if (tid < 64) {
            float t2 = redS[tid];
#pragma unroll
            for (int x2 = 1; x2 < 8; x2++) t2 += redS[x2 * 64 + tid];
            l_sm[tid] = l_sm[tid] * sc_sm[tid] + t2;
        }

        // ---- PV: 4 units. i<2: Vh kc=i*64 (passes Ph,Pl); i>=2: Vl kc=(i-2)*64 (Ph)
        for (int i = 0; i < 4; i++) {
            if (i < 3) {
                int in = i + 1;
                int kcn = (in < 2 ? in : in - 2) * 64;
                const __nv_bfloat16* plane = (in < 2) ? g_Vthi : g_Vtlo;
                const __nv_bfloat16* base = plane + vvo + kb + kcn;
                uint32_t st = sb + OFF_STREAM + (in & 1) * SLOT;
#pragma unroll
                for (int it = 0; it < 4; it++) {
                    int idx = tid + it * 512;
                    int row = idx >> 3, ch = idx & 7;
                    cpa16(st + row * ROWB + ch * 16, base + (size_t)row * Ss + ch * 8);
                }
                asm volatile("cp.async.commit_group;");
                asm volatile("cp.async.wait_group 1;");
            } else {
                asm volatile("cp.async.wait_group 0;");
            }
            __syncthreads();
            uint32_t bbase = sb + OFF_STREAM + (i & 1) * SLOT;
            int kc = (i < 2 ? i : i - 2) * 64;
            int np = (i < 2) ? 2 : 1;
            for (int p = 0; p < np; p++) {
                uint32_t abase = sb + ((i < 2 && p == 1) ? OFF_PL : OFF_PH) + kc * 2;
#pragma unroll
                for (int ks = 0; ks < 4; ks++) {
                    uint32_t a[2][4];
#pragma unroll
                    for (int mf = 0; mf < 2; mf++)
                        ldsm4(a[mf], abase + (wy * 32 + mf * 16 + (lane & 15)) * PROWB +
                                     ks * 32 + (lane >> 4) * 16);
                    uint32_t b[2][4];
#pragma unroll
                    for (int nj = 0; nj < 2; nj++)
                        ldsm4(b[nj], bbase + (wx * 32 + nj * 16 + (lane & 7) + ((lane >> 4) & 1) * 8) * ROWB +
                                     ks * 32 + ((lane >> 3) & 1) * 16);
#pragma unroll
                    for (int mf = 0; mf < 2; mf++)
#pragma unroll
                        for (int nj = 0; nj < 2; nj++) {
                            mma16816(O[mf][nj * 2], a[mf], b[nj][0], b[nj][1]);
                            mma16816(O[mf][nj * 2 + 1], a[mf], b[nj][2], b[nj][3]);
                        }
                }
            }
            __syncthreads();
        }
    }

    // ---- epilogue: O /= l, write concat hi/lo
    int b = z / Hh, h = z % Hh;
#pragma unroll
    for (int mf = 0; mf < 2; mf++) {
        int r0 = wy * 32 + mf * 16 + lr, r1 = r0 + 8;
        float i0 = 1.0f / l_sm[r0], i1 = 1.0f / l_sm[r1];
#pragma unroll
        for (int ni = 0; ni < 4; ni++) {
            int d = wx * 32 + ni * 8 + lc;
            float v00 = O[mf][ni][0] * i0, v01 = O[mf][ni][1] * i0;
            float v10 = O[mf][ni][2] * i1, v11 = O[mf][ni][3] * i1;
            __nv_bfloat16 hh, ll;
            size_t d0 = ((size_t)(b * Ss + rb + r0)) * Ee + h * Dd + d;
            size_t d1 = ((size_t)(b * Ss + rb + r1)) * Ee + h * Dd + d;
            split2(v00, hh, ll); g_Chi[d0] = hh;     g_Clo[d0] = ll;
            split2(v01, hh, ll); g_Chi[d0 + 1] = hh; g_Clo[d0 + 1] = ll;
            split2(v10, hh, ll); g_Chi[d1] = hh;     g_Clo[d1] = ll;
            split2(v11, hh, ll); g_Chi[d1 + 1] = hh; g_Clo[d1 + 1] = ll;
        }
    }
}

// ---------------- out = concat @ Wo + bo ----------------
__global__ __launch_bounds__(256, 2) void mma_out(const float* __restrict__ bo,
                                                  float* __restrict__ out) {
    extern __shared__ __align__(16) char smd[];
    int tid = threadIdx.x, lane = tid & 31, w = tid >> 5;
    int wm = (w & 1) * 64, wn = (w >> 1) * 32;
    uint32_t sbase = smem_u32(smd);
    int rowBase = blockIdx.y * 128, colBase = blockIdx.x * 128;
    float acc[4][4][4] = {};
    Seg seg[3] = {
        { g_Chi + (size_t)rowBase * Ee, g_Wohi + (size_t)colBase * Ee, Ee },
        { g_Clo + (size_t)rowBase * Ee, g_Wohi + (size_t)colBase * Ee, Ee },
        { g_Chi + (size_t)rowBase * Ee, g_Wolo + (size_t)colBase * Ee, Ee } };
    gemm_run(seg, Ee, Ee, sbase, acc, wm, wn, lane);

    int lr = lane >> 2, lc = (lane & 3) * 2;
#pragma unroll
    for (int mi = 0; mi < 4; mi++)
#pragma unroll
        for (int ni = 0; ni < 4; ni++)
#pragma unroll
            for (int half = 0; half < 2; half++) {
                int gr = rowBase + wm + mi * 16 + lr + half * 8;
                int col = colBase + wn + ni * 8 + lc;
                float2 v = make_float2(acc[mi][ni][half * 2] + bo[col],
                                       acc[mi][ni][half * 2 + 1] + bo[col + 1]);
                *(float2*)&out[(size_t)gr * Ee + col] = v;
            }
}

// ---------------- launch ----------------
extern "C" void kernel_launch(void* const* d_in, const int* in_sizes, int n_in,
                              void* d_out, int out_size) {
    const float* Xk = (const float*)d_in[0];
    const float* Xv = (const float*)d_in[1];
    const float* Xq = (const float*)d_in[2];
    const float* WK = (const float*)d_in[3];
    const float* WV = (const float*)d_in[4];
    const float* WQ = (const float*)d_in[5];
    const float* Wo = (const float*)d_in[6];
    const float* bo = (const float*)d_in[7];
    float* out = (float*)d_out;

    cudaFuncSetAttribute(mma_proj, cudaFuncAttributeMaxDynamicSharedMemorySize, SMEM_TOTAL);
    cudaFuncSetAttribute(mma_out, cudaFuncAttributeMaxDynamicSharedMemorySize, SMEM_TOTAL);
    cudaFuncSetAttribute(flash_attn, cudaFuncAttributeMaxDynamicSharedMemorySize, FL_SMEM);

    conv_inputs<<<(NE + 255) / 256, 256>>>(Xk, Xv, Xq);
    conv_weights<<<(EE + 255) / 256, 256>>>(WK, WV, WQ, Wo);

    dim3 gProj(Ee / 128, (Bb * Ss) / 128, 3);  // (6, 64, 3)
    mma_proj<<<gProj, 256, SMEM_TOTAL>>>();

    flash_attn<<<384, FL_THREADS, FL_SMEM>>>();

    dim3 gOut(Ee / 128, (Bb * Ss) / 128);      // (6, 64)
    mma_out<<<gOut, 256, SMEM_TOTAL>>>(bo, out);
}

// round 11
// speedup vs baseline: 1.5081x; 1.5081x over previous
#include <cuda_runtime.h>
#include <cuda_bf16.h>
#include <cstdint>

// ---------------- problem constants ----------------
#define Bb 4
#define Ss 2048
#define Ee 768
#define Hh 3
#define Dd 256
#define BHh 12
#define SCALE 0.022097086912079608f   // 1/sqrt(2048)

#define NE (8192 * 768)
#define EE (768 * 768)

// ---------------- scratch (device globals; no cudaMalloc allowed) ----------------
__device__ __align__(16) __nv_bfloat16 g_Xhi[3][NE];
__device__ __align__(16) __nv_bfloat16 g_Xlo[3][NE];
__device__ __align__(16) __nv_bfloat16 g_Wthi[3][EE];   // W^T: [n=h*256+d][k=e]
__device__ __align__(16) __nv_bfloat16 g_Wtlo[3][EE];
__device__ __align__(16) __nv_bfloat16 g_Wohi[EE];      // Wo^T: [n=eout][k=ein]
__device__ __align__(16) __nv_bfloat16 g_Wolo[EE];
__device__ __align__(16) __nv_bfloat16 g_Qhi[BHh * Ss * Dd];  // [z][s][d]
__device__ __align__(16) __nv_bfloat16 g_Qlo[BHh * Ss * Dd];
__device__ __align__(16) __nv_bfloat16 g_Khi[BHh * Ss * Dd];
__device__ __align__(16) __nv_bfloat16 g_Klo[BHh * Ss * Dd];
__device__ __align__(16) __nv_bfloat16 g_Vthi[BHh * Dd * Ss]; // [z][d][s]
__device__ __align__(16) __nv_bfloat16 g_Vtlo[BHh * Dd * Ss];
__device__ float g_scores[(size_t)BHh * Ss * Ss];
__device__ __align__(16) __nv_bfloat16 g_Phi[(size_t)BHh * Ss * Ss];
__device__ __align__(16) __nv_bfloat16 g_Plo[(size_t)BHh * Ss * Ss];
__device__ __align__(16) __nv_bfloat16 g_Chi[NE];
__device__ __align__(16) __nv_bfloat16 g_Clo[NE];

// ---------------- helpers ----------------
__device__ __forceinline__ uint32_t smem_u32(const void* p) {
    uint32_t a;
    asm("{ .reg .u64 t; cvta.to.shared.u64 t, %1; cvt.u32.u64 %0, t; }" : "=r"(a) : "l"(p));
    return a;
}
__device__ __forceinline__ void ldsm4(uint32_t r[4], uint32_t addr) {
    asm volatile("ldmatrix.sync.aligned.m8n8.x4.shared.b16 {%0,%1,%2,%3}, [%4];"
                 : "=r"(r[0]), "=r"(r[1]), "=r"(r[2]), "=r"(r[3]) : "r"(addr));
}
__device__ __forceinline__ void mma16816(float c[4], const uint32_t a[4], uint32_t b0, uint32_t b1) {
    asm volatile("mma.sync.aligned.m16n8k16.row.col.f32.bf16.bf16.f32 "
                 "{%0,%1,%2,%3}, {%4,%5,%6,%7}, {%8,%9}, {%0,%1,%2,%3};"
                 : "+f"(c[0]), "+f"(c[1]), "+f"(c[2]), "+f"(c[3])
                 : "r"(a[0]), "r"(a[1]), "r"(a[2]), "r"(a[3]), "r"(b0), "r"(b1));
}
__device__ __forceinline__ void split2(float x, __nv_bfloat16& hi, __nv_bfloat16& lo) {
    hi = __float2bfloat16(x);
    lo = __float2bfloat16(x - __bfloat162float(hi));
}

// ---------------- conversion kernels ----------------
__global__ __launch_bounds__(256) void conv_inputs(const float* __restrict__ Xk,
                                                   const float* __restrict__ Xv,
                                                   const float* __restrict__ Xq) {
    int i = blockIdx.x * blockDim.x + threadIdx.x;
    if (i >= NE) return;
    __nv_bfloat16 hi, lo;
    split2(Xk[i], hi, lo); g_Xhi[0][i] = hi; g_Xlo[0][i] = lo;
    split2(Xv[i], hi, lo); g_Xhi[1][i] = hi; g_Xlo[1][i] = lo;
    split2(Xq[i], hi, lo); g_Xhi[2][i] = hi; g_Xlo[2][i] = lo;
}

__global__ __launch_bounds__(256) void conv_weights(const float* __restrict__ WK,
                                                    const float* __restrict__ WV,
                                                    const float* __restrict__ WQ,
                                                    const float* __restrict__ Wo) {
    int i = blockIdx.x * blockDim.x + threadIdx.x;
    if (i >= EE) return;
    int h = i / (Ee * Dd);
    int r = i % (Ee * Dd);
    int e = r / Dd;
    int d = r % Dd;
    int dst = (h * Dd + d) * Ee + e;
    __nv_bfloat16 hi, lo;
    split2(WK[i], hi, lo); g_Wthi[0][dst] = hi; g_Wtlo[0][dst] = lo;
    split2(WV[i], hi, lo); g_Wthi[1][dst] = hi; g_Wtlo[1][dst] = lo;
    split2(WQ[i], hi, lo); g_Wthi[2][dst] = hi; g_Wtlo[2][dst] = lo;
    int k = i / Ee, n = i % Ee;
    split2(Wo[i], hi, lo); g_Wohi[n * Ee + k] = hi; g_Wolo[n * Ee + k] = lo;
}

// ---------------- mma.sync GEMM core: BK=64, 2-stage dynamic-smem pipeline (proven) ----
struct Seg { const __nv_bfloat16* A; const __nv_bfloat16* B; int klen; };

#define ROWB 144
#define HALF_STAGE (128 * ROWB)          // 18432
#define STAGE_BYTES (2 * HALF_STAGE)     // 36864
#define SMEM_TOTAL (2 * STAGE_BYTES)     // 73728

__device__ __forceinline__ void load_tiles(uint32_t st,
                                           const __nv_bfloat16* __restrict__ A, int lda,
                                           const __nv_bfloat16* __restrict__ B, int ldb,
                                           int k0) {
    int tid = threadIdx.x;
#pragma unroll
    for (int c = 0; c < 4; c++) {
        int idx = tid + c * 256;           // 1024 chunks: 128 rows x 8 chunks
        int row = idx >> 3, ch = idx & 7;
        const void* srcA = A + (size_t)row * lda + k0 + ch * 8;
        asm volatile("cp.async.cg.shared.global [%0], [%1], 16;"
                     :: "r"(st + row * ROWB + ch * 16), "l"(srcA));
    }
#pragma unroll
    for (int c = 0; c < 4; c++) {
        int idx = tid + c * 256;
        int row = idx >> 3, ch = idx & 7;
        const void* srcB = B + (size_t)row * ldb + k0 + ch * 8;
        asm volatile("cp.async.cg.shared.global [%0], [%1], 16;"
                     :: "r"(st + HALF_STAGE + row * ROWB + ch * 16), "l"(srcB));
    }
    asm volatile("cp.async.commit_group;");
}

__device__ __forceinline__ void compute_stage(uint32_t st, float acc[4][4][4],
                                              int wm, int wn, int lane) {
    uint32_t sA = st, sB = st + HALF_STAGE;
#pragma unroll
    for (int ks = 0; ks < 4; ks++) {
        uint32_t a[4][4];
#pragma unroll
        for (int mi = 0; mi < 4; mi++) {
            uint32_t addr = sA + (wm + mi * 16 + (lane & 15)) * ROWB + ks * 32 + (lane >> 4) * 16;
            ldsm4(a[mi], addr);
        }
        uint32_t b[2][4];
#pragma unroll
        for (int nj = 0; nj < 2; nj++) {
            uint32_t addr = sB + (wn + nj * 16 + (lane & 7) + ((lane >> 4) & 1) * 8) * ROWB +
                            ks * 32 + ((lane >> 3) & 1) * 16;
            ldsm4(b[nj], addr);
        }
#pragma unroll
        for (int mi = 0; mi < 4; mi++)
#pragma unroll
            for (int ni = 0; ni < 4; ni++)
                mma16816(acc[mi][ni], a[mi], b[ni >> 1][(ni & 1) * 2], b[ni >> 1][(ni & 1) * 2 + 1]);
    }
}

__device__ __forceinline__ void gemm_run(const Seg seg[3], int lda, int ldb,
                                         uint32_t sbase, float acc[4][4][4],
                                         int wm, int wn, int lane) {
    int total = (seg[0].klen + seg[1].klen + seg[2].klen) >> 6;
    int si = 0, k = 0;
    load_tiles(sbase, seg[0].A, lda, seg[0].B, ldb, 0);
    k = 64;
    if (k >= seg[0].klen) { k = 0; si = 1; }
    for (int t = 0; t < total; t++) {
        uint32_t cur = sbase + (t & 1) * STAGE_BYTES;
        if (t + 1 < total) {
            uint32_t nxt = sbase + ((t + 1) & 1) * STAGE_BYTES;
            load_tiles(nxt, seg[si].A, lda, seg[si].B, ldb, k);
            k += 64;
            if (k >= seg[si].klen) { k = 0; si++; }
            asm volatile("cp.async.wait_group 1;");
        } else {
            asm volatile("cp.async.wait_group 0;");
        }
        __syncthreads();
        compute_stage(cur, acc, wm, wn, lane);
        __syncthreads();
    }
}

// ---------------- projections (all 3 fused: blockIdx.z = m) ----------------
__global__ __launch_bounds__(256, 2) void mma_proj() {
    extern __shared__ __align__(16) char smd[];
    int m = blockIdx.z;
    int tid = threadIdx.x, lane = tid & 31, w = tid >> 5;
    int wm = (w & 1) * 64, wn = (w >> 1) * 32;
    uint32_t sbase = smem_u32(smd);
    int rowBase = blockIdx.y * 128, colBase = blockIdx.x * 128;
    float acc[4][4][4] = {};
    Seg seg[3] = {
        { g_Xhi[m] + (size_t)rowBase * Ee, g_Wthi[m] + (size_t)colBase * Ee, Ee },
        { g_Xlo[m] + (size_t)rowBase * Ee, g_Wthi[m] + (size_t)colBase * Ee, Ee },
        { g_Xhi[m] + (size_t)rowBase * Ee, g_Wtlo[m] + (size_t)colBase * Ee, Ee } };
    gemm_run(seg, Ee, Ee, sbase, acc, wm, wn, lane);

    int lr = lane >> 2, lc = (lane & 3) * 2;
#pragma unroll
    for (int mi = 0; mi < 4; mi++)
#pragma unroll
        for (int ni = 0; ni < 4; ni++)
#pragma unroll
            for (int half = 0; half < 2; half++) {
                int gr = rowBase + wm + mi * 16 + lr + half * 8;
                int b = gr >> 11, sI = gr & 2047;
                int col = colBase + wn + ni * 8 + lc;
                int h = col >> 8, d = col & 255;
                int z = b * Hh + h;
                float v0 = acc[mi][ni][half * 2], v1 = acc[mi][ni][half * 2 + 1];
                __nv_bfloat16 h0, l0, h1, l1;
                split2(v0, h0, l0);
                split2(v1, h1, l1);
                if (m == 1) {
                    size_t d0 = ((size_t)z * Dd + d) * Ss + sI;
                    size_t d1 = ((size_t)z * Dd + d + 1) * Ss + sI;
                    g_Vthi[d0] = h0; g_Vtlo[d0] = l0;
                    g_Vthi[d1] = h1; g_Vtlo[d1] = l1;
                } else {
                    size_t dst = ((size_t)z * Ss + sI) * Dd + d;
                    if (m == 0) { g_Khi[dst] = h0; g_Klo[dst] = l0;
                                  g_Khi[dst + 1] = h1; g_Klo[dst + 1] = l1; }
                    else        { g_Qhi[dst] = h0; g_Qlo[dst] = l0;
                                  g_Qhi[dst + 1] = h1; g_Qlo[dst + 1] = l1; }
                }
            }
}

// ---------------- scores = Q K^T * SCALE, compact lower-triangle grid ----------------
// blockIdx.x = t in [0,136) -> (by, bx) with bx <= by
__global__ __launch_bounds__(256, 2) void mma_scores() {
    extern __shared__ __align__(16) char smd[];
    int t = blockIdx.x;
    int by = (int)((sqrtf(8.0f * t + 1.0f) - 1.0f) * 0.5f);
    while ((by + 1) * (by + 2) / 2 <= t) by++;
    while (by * (by + 1) / 2 > t) by--;
    int bx = t - by * (by + 1) / 2;

    int tid = threadIdx.x, lane = tid & 31, w = tid >> 5;
    int wm = (w & 1) * 64, wn = (w >> 1) * 32;
    uint32_t sbase = smem_u32(smd);
    int z = blockIdx.z;
    int rowBase = by * 128, colBase = bx * 128;
    size_t qo = (size_t)z * Ss * Dd;
    const __nv_bfloat16* Qh = g_Qhi + qo + (size_t)rowBase * Dd;
    const __nv_bfloat16* Ql = g_Qlo + qo + (size_t)rowBase * Dd;
    const __nv_bfloat16* Kh = g_Khi + qo + (size_t)colBase * Dd;
    const __nv_bfloat16* Kl = g_Klo + qo + (size_t)colBase * Dd;
    float acc[4][4][4] = {};
    Seg seg[3] = { { Qh, Kh, Dd }, { Ql, Kh, Dd }, { Qh, Kl, Dd } };
    gemm_run(seg, Dd, Dd, sbase, acc, wm, wn, lane);

    float* C = g_scores + (size_t)z * Ss * Ss;
    int lr = lane >> 2, lc = (lane & 3) * 2;
#pragma unroll
    for (int mi = 0; mi < 4; mi++)
#pragma unroll
        for (int ni = 0; ni < 4; ni++)
#pragma unroll
            for (int half = 0; half < 2; half++) {
                int gr = rowBase + wm + mi * 16 + lr + half * 8;
                int col = colBase + wn + ni * 8 + lc;
                float2 v = make_float2(acc[mi][ni][half * 2] * SCALE,
                                       acc[mi][ni][half * 2 + 1] * SCALE);
                *(float2*)&C[(size_t)gr * Ss + col] = v;
            }
}

// ---------------- causal softmax; single pass, P written only up to Lpad ----------------
__global__ __launch_bounds__(256) void softmax_rows() {
    __shared__ float red[8];
    int gid = blockIdx.x;
    int z = gid >> 11;
    int i = gid & 2047;
    size_t ro = (size_t)z * Ss * Ss + (size_t)i * Ss;
    const float* row = g_scores + ro;
    int L = i + 1;
    int Lpad = ((i >> 7) + 1) << 7;   // = kEnd boundary that mma_pv consumes
    int tid = threadIdx.x;
    float v[8];
#pragma unroll
    for (int s = 0; s < 8; s++) {
        int j = tid + s * 256;
        v[s] = (j < L) ? row[j] : -3.4e38f;
    }
    float mx = v[0];
#pragma unroll
    for (int s = 1; s < 8; s++) mx = fmaxf(mx, v[s]);
#pragma unroll
    for (int o = 16; o; o >>= 1) mx = fmaxf(mx, __shfl_xor_sync(0xffffffffu, mx, o));
    if ((tid & 31) == 0) red[tid >> 5] = mx;
    __syncthreads();
    mx = red[0];
#pragma unroll
    for (int ww = 1; ww < 8; ww++) mx = fmaxf(mx, red[ww]);
    __syncthreads();
    float e[8];
    float sum = 0.f;
#pragma unroll
    for (int s = 0; s < 8; s++) {
        int j = tid + s * 256;
        e[s] = (j < L) ? __expf(v[s] - mx) : 0.0f;
        sum += e[s];
    }
#pragma unroll
    for (int o = 16; o; o >>= 1) sum += __shfl_xor_sync(0xffffffffu, sum, o);
    if ((tid & 31) == 0) red[tid >> 5] = sum;
    __syncthreads();
    sum = red[0];
#pragma unroll
    for (int ww = 1; ww < 8; ww++) sum += red[ww];
    float inv = 1.0f / sum;
#pragma unroll
    for (int s = 0; s < 8; s++) {
        int j = tid + s * 256;
        if (j < Lpad) {
            float p = e[s] * inv;
            __nv_bfloat16 hi, lo;
            split2(p, hi, lo);
            g_Phi[ro + j] = hi;
            g_Plo[ro + j] = lo;
        }
    }
}

// ---------------- Z = P V (causal K-limit) -> concat hi/lo; heavy tiles first ----------------
__global__ __launch_bounds__(256, 2) void mma_pv() {
    extern __shared__ __align__(16) char smd[];
    int tid = threadIdx.x, lane = tid & 31, w = tid >> 5;
    int wm = (w & 1) * 64, wn = (w >> 1) * 32;
    uint32_t sbase = smem_u32(smd);
    int z = blockIdx.z;
    // heavy-first: low blockIdx.y (scheduled early) gets the largest kEnd,
    // so the wave-2 stragglers are the lightest tiles.
    int by = 15 - blockIdx.y;
    int rowBase = by * 128, colBase = blockIdx.x * 128;
    int kEnd = rowBase + 128;
    const __nv_bfloat16* Ph = g_Phi + (size_t)z * Ss * Ss + (size_t)rowBase * Ss;
    const __nv_bfloat16* Pl = g_Plo + (size_t)z * Ss * Ss + (size_t)rowBase * Ss;
    const __nv_bfloat16* Vh = g_Vthi + (size_t)z * Dd * Ss + (size_t)colBase * Ss;
    const __nv_bfloat16* Vl = g_Vtlo + (size_t)z * Dd * Ss + (size_t)colBase * Ss;
    float acc[4][4][4] = {};
    Seg seg[3] = { { Ph, Vh, kEnd }, { Pl, Vh, kEnd }, { Ph, Vl, kEnd } };
    gemm_run(seg, Ss, Ss, sbase, acc, wm, wn, lane);

    int b = z / Hh, h = z % Hh;
    int lr = lane >> 2, lc = (lane & 3) * 2;
#pragma unroll
    for (int mi = 0; mi < 4; mi++)
#pragma unroll
        for (int ni = 0; ni < 4; ni++)
#pragma unroll
            for (int half = 0; half < 2; half++) {
                int sI = rowBase + wm + mi * 16 + lr + half * 8;
                int d = colBase + wn + ni * 8 + lc;
                __nv_bfloat16 h0, l0, h1, l1;
                split2(acc[mi][ni][half * 2], h0, l0);
                split2(acc[mi][ni][half * 2 + 1], h1, l1);
                size_t dst = ((size_t)(b * Ss + sI)) * Ee + h * Dd + d;
                g_Chi[dst] = h0; g_Clo[dst] = l0;
                g_Chi[dst + 1] = h1; g_Clo[dst + 1] = l1;
            }
}

// ---------------- out = concat @ Wo + bo ----------------
__global__ __launch_bounds__(256, 2) void mma_out(const float* __restrict__ bo,
                                                  float* __restrict__ out) {
    extern __shared__ __align__(16) char smd[];
    int tid = threadIdx.x, lane = tid & 31, w = tid >> 5;
    int wm = (w & 1) * 64, wn = (w >> 1) * 32;
    uint32_t sbase = smem_u32(smd);
    int rowBase = blockIdx.y * 128, colBase = blockIdx.x * 128;
    float acc[4][4][4] = {};
    Seg seg[3] = {
        { g_Chi + (size_t)rowBase * Ee, g_Wohi + (size_t)colBase * Ee, Ee },
        { g_Clo + (size_t)rowBase * Ee, g_Wohi + (size_t)colBase * Ee, Ee },
        { g_Chi + (size_t)rowBase * Ee, g_Wolo + (size_t)colBase * Ee, Ee } };
    gemm_run(seg, Ee, Ee, sbase, acc, wm, wn, lane);

    int lr = lane >> 2, lc = (lane & 3) * 2;
#pragma unroll
    for (int mi = 0; mi < 4; mi++)
#pragma unroll
        for (int ni = 0; ni < 4; ni++)
#pragma unroll
            for (int half = 0; half < 2; half++) {
                int gr = rowBase + wm + mi * 16 + lr + half * 8;
                int col = colBase + wn + ni * 8 + lc;
                float2 v = make_float2(acc[mi][ni][half * 2] + bo[col],
                                       acc[mi][ni][half * 2 + 1] + bo[col + 1]);
                *(float2*)&out[(size_t)gr * Ee + col] = v;
            }
}

// ---------------- launch ----------------
extern "C" void kernel_launch(void* const* d_in, const int* in_sizes, int n_in,
                              void* d_out, int out_size) {
    const float* Xk = (const float*)d_in[0];
    const float* Xv = (const float*)d_in[1];
    const float* Xq = (const float*)d_in[2];
    const float* WK = (const float*)d_in[3];
    const float* WV = (const float*)d_in[4];
    const float* WQ = (const float*)d_in[5];
    const float* Wo = (const float*)d_in[6];
    const float* bo = (const float*)d_in[7];
    float* out = (float*)d_out;

    // opt-in to >48KB dynamic smem (host-side attribute set; idempotent)
    cudaFuncSetAttribute(mma_proj, cudaFuncAttributeMaxDynamicSharedMemorySize, SMEM_TOTAL);
    cudaFuncSetAttribute(mma_scores, cudaFuncAttributeMaxDynamicSharedMemorySize, SMEM_TOTAL);
    cudaFuncSetAttribute(mma_pv, cudaFuncAttributeMaxDynamicSharedMemorySize, SMEM_TOTAL);
    cudaFuncSetAttribute(mma_out, cudaFuncAttributeMaxDynamicSharedMemorySize, SMEM_TOTAL);

    conv_inputs<<<(NE + 255) / 256, 256>>>(Xk, Xv, Xq);
    conv_weights<<<(EE + 255) / 256, 256>>>(WK, WV, WQ, Wo);

    dim3 gProj(Ee / 128, (Bb * Ss) / 128, 3);  // (6, 64, 3) — all projections in one launch
    mma_proj<<<gProj, 256, SMEM_TOTAL>>>();

    dim3 gSc(136, 1, BHh);                     // compact lower triangle: 136 tiles x 12
    mma_scores<<<gSc, 256, SMEM_TOTAL>>>();

    softmax_rows<<<BHh * Ss, 256>>>();

    dim3 gPv(Dd / 128, Ss / 128, BHh);         // (2, 16, 12), heavy-first row mapping
    mma_pv<<<gPv, 256, SMEM_TOTAL>>>();

    dim3 gOut(Ee / 128, (Bb * Ss) / 128);      // (6, 64)
    mma_out<<<gOut, 256, SMEM_TOTAL>>>(bo, out);
}

// round 13
// speedup vs baseline: 1.6636x; 1.1031x over previous
#include <cuda_runtime.h>
#include <cuda_bf16.h>
#include <cstdint>

// ---------------- problem constants ----------------
#define Bb 4
#define Ss 2048
#define Ee 768
#define Hh 3
#define Dd 256
#define BHh 12
#define SCALE 0.022097086912079608f   // 1/sqrt(2048)

#define NE (8192 * 768)
#define EE (768 * 768)

// ---------------- scratch (device globals; no cudaMalloc allowed) ----------------
__device__ __align__(16) __nv_bfloat16 g_Xhi[3][NE];
__device__ __align__(16) __nv_bfloat16 g_Xlo[3][NE];
__device__ __align__(16) __nv_bfloat16 g_Wthi[3][EE];   // W^T: [n=h*256+d][k=e]
__device__ __align__(16) __nv_bfloat16 g_Wtlo[3][EE];
__device__ __align__(16) __nv_bfloat16 g_Wohi[EE];      // Wo^T: [n=eout][k=ein]
__device__ __align__(16) __nv_bfloat16 g_Wolo[EE];
__device__ __align__(16) __nv_bfloat16 g_Qhi[BHh * Ss * Dd];  // [z][s][d]
__device__ __align__(16) __nv_bfloat16 g_Khi[BHh * Ss * Dd];
__device__ __align__(16) __nv_bfloat16 g_Vthi[BHh * Dd * Ss]; // [z][d][s]
__device__ __align__(16) __nv_bfloat16 g_Vtlo[BHh * Dd * Ss];
__device__ float g_scores[(size_t)BHh * Ss * Ss];
__device__ __align__(16) __nv_bfloat16 g_Phi[(size_t)BHh * Ss * Ss];
__device__ __align__(16) __nv_bfloat16 g_Plo[(size_t)BHh * Ss * Ss];
__device__ __align__(16) __nv_bfloat16 g_Chi[NE];
__device__ __align__(16) __nv_bfloat16 g_Clo[NE];

// ---------------- helpers ----------------
__device__ __forceinline__ uint32_t smem_u32(const void* p) {
    uint32_t a;
    asm("{ .reg .u64 t; cvta.to.shared.u64 t, %1; cvt.u32.u64 %0, t; }" : "=r"(a) : "l"(p));
    return a;
}
__device__ __forceinline__ void ldsm4(uint32_t r[4], uint32_t addr) {
    asm volatile("ldmatrix.sync.aligned.m8n8.x4.shared.b16 {%0,%1,%2,%3}, [%4];"
                 : "=r"(r[0]), "=r"(r[1]), "=r"(r[2]), "=r"(r[3]) : "r"(addr));
}
__device__ __forceinline__ void mma16816(float c[4], const uint32_t a[4], uint32_t b0, uint32_t b1) {
    asm volatile("mma.sync.aligned.m16n8k16.row.col.f32.bf16.bf16.f32 "
                 "{%0,%1,%2,%3}, {%4,%5,%6,%7}, {%8,%9}, {%0,%1,%2,%3};"
                 : "+f"(c[0]), "+f"(c[1]), "+f"(c[2]), "+f"(c[3])
                 : "r"(a[0]), "r"(a[1]), "r"(a[2]), "r"(a[3]), "r"(b0), "r"(b1));
}
__device__ __forceinline__ void split2(float x, __nv_bfloat16& hi, __nv_bfloat16& lo) {
    hi = __float2bfloat16(x);
    lo = __float2bfloat16(x - __bfloat162float(hi));
}

// ---------------- conversion kernels ----------------
__global__ __launch_bounds__(256) void conv_inputs(const float* __restrict__ Xk,
                                                   const float* __restrict__ Xv,
                                                   const float* __restrict__ Xq) {
    int i = blockIdx.x * blockDim.x + threadIdx.x;
    if (i >= NE) return;
    __nv_bfloat16 hi, lo;
    split2(Xk[i], hi, lo); g_Xhi[0][i] = hi; g_Xlo[0][i] = lo;
    split2(Xv[i], hi, lo); g_Xhi[1][i] = hi; g_Xlo[1][i] = lo;
    split2(Xq[i], hi, lo); g_Xhi[2][i] = hi; g_Xlo[2][i] = lo;
}

__global__ __launch_bounds__(256) void conv_weights(const float* __restrict__ WK,
                                                    const float* __restrict__ WV,
                                                    const float* __restrict__ WQ,
                                                    const float* __restrict__ Wo) {
    int i = blockIdx.x * blockDim.x + threadIdx.x;
    if (i >= EE) return;
    int h = i / (Ee * Dd);
    int r = i % (Ee * Dd);
    int e = r / Dd;
    int d = r % Dd;
    int dst = (h * Dd + d) * Ee + e;
    __nv_bfloat16 hi, lo;
    split2(WK[i], hi, lo); g_Wthi[0][dst] = hi; g_Wtlo[0][dst] = lo;
    split2(WV[i], hi, lo); g_Wthi[1][dst] = hi; g_Wtlo[1][dst] = lo;
    split2(WQ[i], hi, lo); g_Wthi[2][dst] = hi; g_Wtlo[2][dst] = lo;
    int k = i / Ee, n = i % Ee;
    split2(Wo[i], hi, lo); g_Wohi[n * Ee + k] = hi; g_Wolo[n * Ee + k] = lo;
}

// ---------------- mma.sync GEMM core: BK=64, 2-stage dynamic-smem pipeline (proven) ----
struct Seg { const __nv_bfloat16* A; const __nv_bfloat16* B; int klen; };

#define ROWB 144
#define HALF_STAGE (128 * ROWB)          // 18432
#define STAGE_BYTES (2 * HALF_STAGE)     // 36864
#define SMEM_TOTAL (2 * STAGE_BYTES)     // 73728

__device__ __forceinline__ void load_tiles(uint32_t st,
                                           const __nv_bfloat16* __restrict__ A, int lda,
                                           const __nv_bfloat16* __restrict__ B, int ldb,
                                           int k0) {
    int tid = threadIdx.x;
#pragma unroll
    for (int c = 0; c < 4; c++) {
        int idx = tid + c * 256;           // 1024 chunks: 128 rows x 8 chunks
        int row = idx >> 3, ch = idx & 7;
        const void* srcA = A + (size_t)row * lda + k0 + ch * 8;
        asm volatile("cp.async.cg.shared.global [%0], [%1], 16;"
                     :: "r"(st + row * ROWB + ch * 16), "l"(srcA));
    }
#pragma unroll
    for (int c = 0; c < 4; c++) {
        int idx = tid + c * 256;
        int row = idx >> 3, ch = idx & 7;
        const void* srcB = B + (size_t)row * ldb + k0 + ch * 8;
        asm volatile("cp.async.cg.shared.global [%0], [%1], 16;"
                     :: "r"(st + HALF_STAGE + row * ROWB + ch * 16), "l"(srcB));
    }
    asm volatile("cp.async.commit_group;");
}

__device__ __forceinline__ void compute_stage(uint32_t st, float acc[4][4][4],
                                              int wm, int wn, int lane) {
    uint32_t sA = st, sB = st + HALF_STAGE;
#pragma unroll
    for (int ks = 0; ks < 4; ks++) {
        uint32_t a[4][4];
#pragma unroll
        for (int mi = 0; mi < 4; mi++) {
            uint32_t addr = sA + (wm + mi * 16 + (lane & 15)) * ROWB + ks * 32 + (lane >> 4) * 16;
            ldsm4(a[mi], addr);
        }
        uint32_t b[2][4];
#pragma unroll
        for (int nj = 0; nj < 2; nj++) {
            uint32_t addr = sB + (wn + nj * 16 + (lane & 7) + ((lane >> 4) & 1) * 8) * ROWB +
                            ks * 32 + ((lane >> 3) & 1) * 16;
            ldsm4(b[nj], addr);
        }
#pragma unroll
        for (int mi = 0; mi < 4; mi++)
#pragma unroll
            for (int ni = 0; ni < 4; ni++)
                mma16816(acc[mi][ni], a[mi], b[ni >> 1][(ni & 1) * 2], b[ni >> 1][(ni & 1) * 2 + 1]);
    }
}

__device__ __forceinline__ void gemm_run(const Seg seg[3], int lda, int ldb,
                                         uint32_t sbase, float acc[4][4][4],
                                         int wm, int wn, int lane) {
    int total = (seg[0].klen + seg[1].klen + seg[2].klen) >> 6;
    int si = 0, k = 0;
    load_tiles(sbase, seg[0].A, lda, seg[0].B, ldb, 0);
    k = 64;
    if (k >= seg[0].klen) { k = 0; si = 1; }
    for (int t = 0; t < total; t++) {
        uint32_t cur = sbase + (t & 1) * STAGE_BYTES;
        if (t + 1 < total) {
            uint32_t nxt = sbase + ((t + 1) & 1) * STAGE_BYTES;
            load_tiles(nxt, seg[si].A, lda, seg[si].B, ldb, k);
            k += 64;
            if (k >= seg[si].klen) { k = 0; si++; }
            asm volatile("cp.async.wait_group 1;");
        } else {
            asm volatile("cp.async.wait_group 0;");
        }
        __syncthreads();
        compute_stage(cur, acc, wm, wn, lane);
        __syncthreads();
    }
}

// ---------------- projections (all 3 fused: blockIdx.z = m) ----------------
__global__ __launch_bounds__(256, 2) void mma_proj() {
    extern __shared__ __align__(16) char smd[];
    int m = blockIdx.z;
    int tid = threadIdx.x, lane = tid & 31, w = tid >> 5;
    int wm = (w & 1) * 64, wn = (w >> 1) * 32;
    uint32_t sbase = smem_u32(smd);
    int rowBase = blockIdx.y * 128, colBase = blockIdx.x * 128;
    float acc[4][4][4] = {};
    Seg seg[3] = {
        { g_Xhi[m] + (size_t)rowBase * Ee, g_Wthi[m] + (size_t)colBase * Ee, Ee },
        { g_Xlo[m] + (size_t)rowBase * Ee, g_Wthi[m] + (size_t)colBase * Ee, Ee },
        { g_Xhi[m] + (size_t)rowBase * Ee, g_Wtlo[m] + (size_t)colBase * Ee, Ee } };
    gemm_run(seg, Ee, Ee, sbase, acc, wm, wn, lane);

    int lr = lane >> 2, lc = (lane & 3) * 2;
#pragma unroll
    for (int mi = 0; mi < 4; mi++)
#pragma unroll
        for (int ni = 0; ni < 4; ni++)
#pragma unroll
            for (int half = 0; half < 2; half++) {
                int gr = rowBase + wm + mi * 16 + lr + half * 8;
                int b = gr >> 11, sI = gr & 2047;
                int col = colBase + wn + ni * 8 + lc;
                int h = col >> 8, d = col & 255;
                int z = b * Hh + h;
                float v0 = acc[mi][ni][half * 2], v1 = acc[mi][ni][half * 2 + 1];
                if (m == 1) {
                    __nv_bfloat16 h0, l0, h1, l1;
                    split2(v0, h0, l0);
                    split2(v1, h1, l1);
                    size_t d0 = ((size_t)z * Dd + d) * Ss + sI;
                    size_t d1 = ((size_t)z * Dd + d + 1) * Ss + sI;
                    g_Vthi[d0] = h0; g_Vtlo[d0] = l0;
                    g_Vthi[d1] = h1; g_Vtlo[d1] = l1;
                } else {
                    // scores GEMM is single-pass bf16: only hi planes needed
                    size_t dst = ((size_t)z * Ss + sI) * Dd + d;
                    __nv_bfloat16 h0 = __float2bfloat16(v0);
                    __nv_bfloat16 h1 = __float2bfloat16(v1);
                    if (m == 0) { g_Khi[dst] = h0; g_Khi[dst + 1] = h1; }
                    else        { g_Qhi[dst] = h0; g_Qhi[dst + 1] = h1; }
                }
            }
}

// ---------------- scores = Q K^T * SCALE, compact lower-triangle grid, single bf16 pass ----
// blockIdx.x = t in [0,136) -> (by, bx) with bx <= by
__global__ __launch_bounds__(256, 2) void mma_scores() {
    extern __shared__ __align__(16) char smd[];
    int t = blockIdx.x;
    int by = (int)((sqrtf(8.0f * t + 1.0f) - 1.0f) * 0.5f);
    while ((by + 1) * (by + 2) / 2 <= t) by++;
    while (by * (by + 1) / 2 > t) by--;
    int bx = t - by * (by + 1) / 2;

    int tid = threadIdx.x, lane = tid & 31, w = tid >> 5;
    int wm = (w & 1) * 64, wn = (w >> 1) * 32;
    uint32_t sbase = smem_u32(smd);
    int z = blockIdx.z;
    int rowBase = by * 128, colBase = bx * 128;
    size_t qo = (size_t)z * Ss * Dd;
    const __nv_bfloat16* Qh = g_Qhi + qo + (size_t)rowBase * Dd;
    const __nv_bfloat16* Kh = g_Khi + qo + (size_t)colBase * Dd;
    float acc[4][4][4] = {};
    Seg seg[3] = { { Qh, Kh, Dd }, { Qh, Kh, 0 }, { Qh, Kh, 0 } };
    gemm_run(seg, Dd, Dd, sbase, acc, wm, wn, lane);

    float* C = g_scores + (size_t)z * Ss * Ss;
    int lr = lane >> 2, lc = (lane & 3) * 2;
#pragma unroll
    for (int mi = 0; mi < 4; mi++)
#pragma unroll
        for (int ni = 0; ni < 4; ni++)
#pragma unroll
            for (int half = 0; half < 2; half++) {
                int gr = rowBase + wm + mi * 16 + lr + half * 8;
                int col = colBase + wn + ni * 8 + lc;
                float2 v = make_float2(acc[mi][ni][half * 2] * SCALE,
                                       acc[mi][ni][half * 2 + 1] * SCALE);
                *(float2*)&C[(size_t)gr * Ss + col] = v;
            }
}

// ---------------- causal softmax; single pass, heavy rows first, P up to Lpad ----------------
__global__ __launch_bounds__(256) void softmax_rows() {
    __shared__ float red[8];
    int gid = blockIdx.x;
    int z = gid >> 11;
    int i = 2047 - (gid & 2047);      // heavy rows scheduled first
    size_t ro = (size_t)z * Ss * Ss + (size_t)i * Ss;
    const float* row = g_scores + ro;
    int L = i + 1;
    int Lpad = ((i >> 7) + 1) << 7;   // = kEnd boundary that mma_pv consumes
    int tid = threadIdx.x;
    float v[8];
#pragma unroll
    for (int s = 0; s < 8; s++) {
        int j = tid + s * 256;
        v[s] = (j < L) ? row[j] : -3.4e38f;
    }
    float mx = v[0];
#pragma unroll
    for (int s = 1; s < 8; s++) mx = fmaxf(mx, v[s]);
#pragma unroll
    for (int o = 16; o; o >>= 1) mx = fmaxf(mx, __shfl_xor_sync(0xffffffffu, mx, o));
    if ((tid & 31) == 0) red[tid >> 5] = mx;
    __syncthreads();
    mx = red[0];
#pragma unroll
    for (int ww = 1; ww < 8; ww++) mx = fmaxf(mx, red[ww]);
    __syncthreads();
    float e[8];
    float sum = 0.f;
#pragma unroll
    for (int s = 0; s < 8; s++) {
        int j = tid + s * 256;
        e[s] = (j < L) ? __expf(v[s] - mx) : 0.0f;
        sum += e[s];
    }
#pragma unroll
    for (int o = 16; o; o >>= 1) sum += __shfl_xor_sync(0xffffffffu, sum, o);
    if ((tid & 31) == 0) red[tid >> 5] = sum;
    __syncthreads();
    sum = red[0];
#pragma unroll
    for (int ww = 1; ww < 8; ww++) sum += red[ww];
    float inv = 1.0f / sum;
#pragma unroll
    for (int s = 0; s < 8; s++) {
        int j = tid + s * 256;
        if (j < Lpad) {
            float p = e[s] * inv;
            __nv_bfloat16 hi, lo;
            split2(p, hi, lo);
            g_Phi[ro + j] = hi;
            g_Plo[ro + j] = lo;
        }
    }
}

// ---------------- Z = P V (causal K-limit) -> concat hi/lo; heavy tiles first ----------------
__global__ __launch_bounds__(256, 2) void mma_pv() {
    extern __shared__ __align__(16) char smd[];
    int tid = threadIdx.x, lane = tid & 31, w = tid >> 5;
    int wm = (w & 1) * 64, wn = (w >> 1) * 32;
    uint32_t sbase = smem_u32(smd);
    int z = blockIdx.z;
    int by = 15 - blockIdx.y;          // heavy-first
    int rowBase = by * 128, colBase = blockIdx.x * 128;
    int kEnd = rowBase + 128;
    const __nv_bfloat16* Ph = g_Phi + (size_t)z * Ss * Ss + (size_t)rowBase * Ss;
    const __nv_bfloat16* Pl = g_Plo + (size_t)z * Ss * Ss + (size_t)rowBase * Ss;
    const __nv_bfloat16* Vh = g_Vthi + (size_t)z * Dd * Ss + (size_t)colBase * Ss;
    const __nv_bfloat16* Vl = g_Vtlo + (size_t)z * Dd * Ss + (size_t)colBase * Ss;
    float acc[4][4][4] = {};
    Seg seg[3] = { { Ph, Vh, kEnd }, { Pl, Vh, kEnd }, { Ph, Vl, kEnd } };
    gemm_run(seg, Ss, Ss, sbase, acc, wm, wn, lane);

    int b = z / Hh, h = z % Hh;
    int lr = lane >> 2, lc = (lane & 3) * 2;
#pragma unroll
    for (int mi = 0; mi < 4; mi++)
#pragma unroll
        for (int ni = 0; ni < 4; ni++)
#pragma unroll
            for (int half = 0; half < 2; half++) {
                int sI = rowBase + wm + mi * 16 + lr + half * 8;
                int d = colBase + wn + ni * 8 + lc;
                __nv_bfloat16 h0, l0, h1, l1;
                split2(acc[mi][ni][half * 2], h0, l0);
                split2(acc[mi][ni][half * 2 + 1], h1, l1);
                size_t dst = ((size_t)(b * Ss + sI)) * Ee + h * Dd + d;
                g_Chi[dst] = h0; g_Clo[dst] = l0;
                g_Chi[dst + 1] = h1; g_Clo[dst + 1] = l1;
            }
}

// ---------------- out = concat @ Wo + bo ----------------
__global__ __launch_bounds__(256, 2) void mma_out(const float* __restrict__ bo,
                                                  float* __restrict__ out) {
    extern __shared__ __align__(16) char smd[];
    int tid = threadIdx.x, lane = tid & 31, w = tid >> 5;
    int wm = (w & 1) * 64, wn = (w >> 1) * 32;
    uint32_t sbase = smem_u32(smd);
    int rowBase = blockIdx.y * 128, colBase = blockIdx.x * 128;
    float acc[4][4][4] = {};
    Seg seg[3] = {
        { g_Chi + (size_t)rowBase * Ee, g_Wohi + (size_t)colBase * Ee, Ee },
        { g_Clo + (size_t)rowBase * Ee, g_Wohi + (size_t)colBase * Ee, Ee },
        { g_Chi + (size_t)rowBase * Ee, g_Wolo + (size_t)colBase * Ee, Ee } };
    gemm_run(seg, Ee, Ee, sbase, acc, wm, wn, lane);

    int lr = lane >> 2, lc = (lane & 3) * 2;
#pragma unroll
    for (int mi = 0; mi < 4; mi++)
#pragma unroll
        for (int ni = 0; ni < 4; ni++)
#pragma unroll
            for (int half = 0; half < 2; half++) {
                int gr = rowBase + wm + mi * 16 + lr + half * 8;
                int col = colBase + wn + ni * 8 + lc;
                float2 v = make_float2(acc[mi][ni][half * 2] + bo[col],
                                       acc[mi][ni][half * 2 + 1] + bo[col + 1]);
                *(float2*)&out[(size_t)gr * Ee + col] = v;
            }
}

// ---------------- launch ----------------
extern "C" void kernel_launch(void* const* d_in, const int* in_sizes, int n_in,
                              void* d_out, int out_size) {
    const float* Xk = (const float*)d_in[0];
    const float* Xv = (const float*)d_in[1];
    const float* Xq = (const float*)d_in[2];
    const float* WK = (const float*)d_in[3];
    const float* WV = (const float*)d_in[4];
    const float* WQ = (const float*)d_in[5];
    const float* Wo = (const float*)d_in[6];
    const float* bo = (const float*)d_in[7];
    float* out = (float*)d_out;

    // opt-in to >48KB dynamic smem (host-side attribute set; idempotent)
    cudaFuncSetAttribute(mma_proj, cudaFuncAttributeMaxDynamicSharedMemorySize, SMEM_TOTAL);
    cudaFuncSetAttribute(mma_scores, cudaFuncAttributeMaxDynamicSharedMemorySize, SMEM_TOTAL);
    cudaFuncSetAttribute(mma_pv, cudaFuncAttributeMaxDynamicSharedMemorySize, SMEM_TOTAL);
    cudaFuncSetAttribute(mma_out, cudaFuncAttributeMaxDynamicSharedMemorySize, SMEM_TOTAL);

    conv_inputs<<<(NE + 255) / 256, 256>>>(Xk, Xv, Xq);
    conv_weights<<<(EE + 255) / 256, 256>>>(WK, WV, WQ, Wo);

    dim3 gProj(Ee / 128, (Bb * Ss) / 128, 3);  // (6, 64, 3) — all projections in one launch
    mma_proj<<<gProj, 256, SMEM_TOTAL>>>();

    dim3 gSc(136, 1, BHh);                     // compact lower triangle: 136 tiles x 12
    mma_scores<<<gSc, 256, SMEM_TOTAL>>>();

    softmax_rows<<<BHh * Ss, 256>>>();

    dim3 gPv(Dd / 128, Ss / 128, BHh);         // (2, 16, 12), heavy-first row mapping
    mma_pv<<<gPv, 256, SMEM_TOTAL>>>();

    dim3 gOut(Ee / 128, (Bb * Ss) / 128);      // (6, 64)
    mma_out<<<gOut, 256, SMEM_TOTAL>>>(bo, out);
}

// round 17
// speedup vs baseline: 2.0018x; 1.2033x over previous
#include <cuda_runtime.h>
#include <cuda_bf16.h>
#include <cstdint>

// ---------------- problem constants ----------------
#define Bb 4
#define Ss 2048
#define Ee 768
#define Hh 3
#define Dd 256
#define BHh 12
#define SCALE 0.022097086912079608f   // 1/sqrt(2048)

#define NE (8192 * 768)
#define EE (768 * 768)

// ---------------- scratch (device globals; no cudaMalloc allowed) ----------------
__device__ __align__(16) __nv_bfloat16 g_Xhi[3][NE];
__device__ __align__(16) __nv_bfloat16 g_Xlo[3][NE];    // only [1] (V input) written/used
__device__ __align__(16) __nv_bfloat16 g_Wthi[3][EE];   // W^T: [n=h*256+d][k=e]
__device__ __align__(16) __nv_bfloat16 g_Wtlo[3][EE];   // only [1] written/used
__device__ __align__(16) __nv_bfloat16 g_Wohi[EE];      // Wo^T: [n=eout][k=ein]
__device__ __align__(16) __nv_bfloat16 g_Wolo[EE];
__device__ __align__(16) __nv_bfloat16 g_Qhi[BHh * Ss * Dd];  // [z][s][d]
__device__ __align__(16) __nv_bfloat16 g_Khi[BHh * Ss * Dd];
__device__ __align__(16) __nv_bfloat16 g_Vthi[BHh * Dd * Ss]; // [z][d][s]
__device__ __align__(16) __nv_bfloat16 g_Vtlo[BHh * Dd * Ss];
__device__ __align__(16) __nv_bfloat16 g_scores[(size_t)BHh * Ss * Ss];  // bf16 logits
__device__ __align__(16) __nv_bfloat16 g_Phi[(size_t)BHh * Ss * Ss];
__device__ __align__(16) __nv_bfloat16 g_Plo[(size_t)BHh * Ss * Ss];
__device__ __align__(16) __nv_bfloat16 g_Chi[NE];
__device__ __align__(16) __nv_bfloat16 g_Clo[NE];

// ---------------- helpers ----------------
__device__ __forceinline__ uint32_t smem_u32(const void* p) {
    uint32_t a;
    asm("{ .reg .u64 t; cvta.to.shared.u64 t, %1; cvt.u32.u64 %0, t; }" : "=r"(a) : "l"(p));
    return a;
}
__device__ __forceinline__ void ldsm4(uint32_t r[4], uint32_t addr) {
    asm volatile("ldmatrix.sync.aligned.m8n8.x4.shared.b16 {%0,%1,%2,%3}, [%4];"
                 : "=r"(r[0]), "=r"(r[1]), "=r"(r[2]), "=r"(r[3]) : "r"(addr));
}
__device__ __forceinline__ void mma16816(float c[4], const uint32_t a[4], uint32_t b0, uint32_t b1) {
    asm volatile("mma.sync.aligned.m16n8k16.row.col.f32.bf16.bf16.f32 "
                 "{%0,%1,%2,%3}, {%4,%5,%6,%7}, {%8,%9}, {%0,%1,%2,%3};"
                 : "+f"(c[0]), "+f"(c[1]), "+f"(c[2]), "+f"(c[3])
                 : "r"(a[0]), "r"(a[1]), "r"(a[2]), "r"(a[3]), "r"(b0), "r"(b1));
}
__device__ __forceinline__ void split2(float x, __nv_bfloat16& hi, __nv_bfloat16& lo) {
    hi = __float2bfloat16(x);
    lo = __float2bfloat16(x - __bfloat162float(hi));
}

// ---------------- conversion kernels ----------------
__global__ __launch_bounds__(256) void conv_inputs(const float* __restrict__ Xk,
                                                   const float* __restrict__ Xv,
                                                   const float* __restrict__ Xq) {
    int i = blockIdx.x * blockDim.x + threadIdx.x;
    if (i >= NE) return;
    __nv_bfloat16 hi, lo;
    // K/Q inputs: hi only (their projections are single-pass)
    g_Xhi[0][i] = __float2bfloat16(Xk[i]);
    g_Xhi[2][i] = __float2bfloat16(Xq[i]);
    split2(Xv[i], hi, lo); g_Xhi[1][i] = hi; g_Xlo[1][i] = lo;
}

__global__ __launch_bounds__(256) void conv_weights(const float* __restrict__ WK,
                                                    const float* __restrict__ WV,
                                                    const float* __restrict__ WQ,
                                                    const float* __restrict__ Wo) {
    int i = blockIdx.x * blockDim.x + threadIdx.x;
    if (i >= EE) return;
    int h = i / (Ee * Dd);
    int r = i % (Ee * Dd);
    int e = r / Dd;
    int d = r % Dd;
    int dst = (h * Dd + d) * Ee + e;
    __nv_bfloat16 hi, lo;
    g_Wthi[0][dst] = __float2bfloat16(WK[i]);
    g_Wthi[2][dst] = __float2bfloat16(WQ[i]);
    split2(WV[i], hi, lo); g_Wthi[1][dst] = hi; g_Wtlo[1][dst] = lo;
    int k = i / Ee, n = i % Ee;
    split2(Wo[i], hi, lo); g_Wohi[n * Ee + k] = hi; g_Wolo[n * Ee + k] = lo;
}

// ---------------- mma.sync GEMM core: BK=64, 2-stage dynamic-smem pipeline (proven) ----
struct Seg { const __nv_bfloat16* A; const __nv_bfloat16* B; int klen; };

#define ROWB 144
#define HALF_STAGE (128 * ROWB)          // 18432
#define STAGE_BYTES (2 * HALF_STAGE)     // 36864
#define SMEM_TOTAL (2 * STAGE_BYTES)     // 73728

__device__ __forceinline__ void load_tiles(uint32_t st,
                                           const __nv_bfloat16* __restrict__ A, int lda,
                                           const __nv_bfloat16* __restrict__ B, int ldb,
                                           int k0) {
    int tid = threadIdx.x;
#pragma unroll
    for (int c = 0; c < 4; c++) {
        int idx = tid + c * 256;           // 1024 chunks: 128 rows x 8 chunks
        int row = idx >> 3, ch = idx & 7;
        const void* srcA = A + (size_t)row * lda + k0 + ch * 8;
        asm volatile("cp.async.cg.shared.global [%0], [%1], 16;"
                     :: "r"(st + row * ROWB + ch * 16), "l"(srcA));
    }
#pragma unroll
    for (int c = 0; c < 4; c++) {
        int idx = tid + c * 256;
        int row = idx >> 3, ch = idx & 7;
        const void* srcB = B + (size_t)row * ldb + k0 + ch * 8;
        asm volatile("cp.async.cg.shared.global [%0], [%1], 16;"
                     :: "r"(st + HALF_STAGE + row * ROWB + ch * 16), "l"(srcB));
    }
    asm volatile("cp.async.commit_group;");
}

__device__ __forceinline__ void compute_stage(uint32_t st, float acc[4][4][4],
                                              int wm, int wn, int lane) {
    uint32_t sA = st, sB = st + HALF_STAGE;
#pragma unroll
    for (int ks = 0; ks < 4; ks++) {
        uint32_t a[4][4];
#pragma unroll
        for (int mi = 0; mi < 4; mi++) {
            uint32_t addr = sA + (wm + mi * 16 + (lane & 15)) * ROWB + ks * 32 + (lane >> 4) * 16;
            ldsm4(a[mi], addr);
        }
        uint32_t b[2][4];
#pragma unroll
        for (int nj = 0; nj < 2; nj++) {
            uint32_t addr = sB + (wn + nj * 16 + (lane & 7) + ((lane >> 4) & 1) * 8) * ROWB +
                            ks * 32 + ((lane >> 3) & 1) * 16;
            ldsm4(b[nj], addr);
        }
#pragma unroll
        for (int mi = 0; mi < 4; mi++)
#pragma unroll
            for (int ni = 0; ni < 4; ni++)
                mma16816(acc[mi][ni], a[mi], b[ni >> 1][(ni & 1) * 2], b[ni >> 1][(ni & 1) * 2 + 1]);
    }
}

__device__ __forceinline__ void gemm_run(const Seg seg[3], int lda, int ldb,
                                         uint32_t sbase, float acc[4][4][4],
                                         int wm, int wn, int lane) {
    int total = (seg[0].klen + seg[1].klen + seg[2].klen) >> 6;
    int si = 0, k = 0;
    load_tiles(sbase, seg[0].A, lda, seg[0].B, ldb, 0);
    k = 64;
    if (k >= seg[0].klen) { k = 0; si = 1; }
    for (int t = 0; t < total; t++) {
        uint32_t cur = sbase + (t & 1) * STAGE_BYTES;
        if (t + 1 < total) {
            uint32_t nxt = sbase + ((t + 1) & 1) * STAGE_BYTES;
            load_tiles(nxt, seg[si].A, lda, seg[si].B, ldb, k);
            k += 64;
            if (k >= seg[si].klen) { k = 0; si++; }
            asm volatile("cp.async.wait_group 1;");
        } else {
            asm volatile("cp.async.wait_group 0;");
        }
        __syncthreads();
        compute_stage(cur, acc, wm, wn, lane);
        __syncthreads();
    }
}

// ---------------- projections (all 3 fused; V single-pass-heavy first) ----------------
// zz=0 -> m=1 (V, 3-pass, heavy); zz=1 -> m=0 (K, 1-pass); zz=2 -> m=2 (Q, 1-pass)
__global__ __launch_bounds__(256, 2) void mma_proj() {
    extern __shared__ __align__(16) char smd[];
    int zz = blockIdx.z;
    int m = (zz == 0) ? 1 : (zz == 1 ? 0 : 2);
    int tid = threadIdx.x, lane = tid & 31, w = tid >> 5;
    int wm = (w & 1) * 64, wn = (w >> 1) * 32;
    uint32_t sbase = smem_u32(smd);
    int rowBase = blockIdx.y * 128, colBase = blockIdx.x * 128;
    float acc[4][4][4] = {};
    Seg seg[3];
    const __nv_bfloat16* Xh = g_Xhi[m] + (size_t)rowBase * Ee;
    const __nv_bfloat16* Wh = g_Wthi[m] + (size_t)colBase * Ee;
    if (m == 1) {
        seg[0] = { Xh, Wh, Ee };
        seg[1] = { g_Xlo[1] + (size_t)rowBase * Ee, Wh, Ee };
        seg[2] = { Xh, g_Wtlo[1] + (size_t)colBase * Ee, Ee };
    } else {
        seg[0] = { Xh, Wh, Ee };
        seg[1] = { Xh, Wh, 0 };
        seg[2] = { Xh, Wh, 0 };
    }
    gemm_run(seg, Ee, Ee, sbase, acc, wm, wn, lane);

    int lr = lane >> 2, lc = (lane & 3) * 2;
#pragma unroll
    for (int mi = 0; mi < 4; mi++)
#pragma unroll
        for (int ni = 0; ni < 4; ni++)
#pragma unroll
            for (int half = 0; half < 2; half++) {
                int gr = rowBase + wm + mi * 16 + lr + half * 8;
                int b = gr >> 11, sI = gr & 2047;
                int col = colBase + wn + ni * 8 + lc;
                int h = col >> 8, d = col & 255;
                int z = b * Hh + h;
                float v0 = acc[mi][ni][half * 2], v1 = acc[mi][ni][half * 2 + 1];
                if (m == 1) {
                    __nv_bfloat16 h0, l0, h1, l1;
                    split2(v0, h0, l0);
                    split2(v1, h1, l1);
                    size_t d0 = ((size_t)z * Dd + d) * Ss + sI;
                    size_t d1 = ((size_t)z * Dd + d + 1) * Ss + sI;
                    g_Vthi[d0] = h0; g_Vtlo[d0] = l0;
                    g_Vthi[d1] = h1; g_Vtlo[d1] = l1;
                } else {
                    size_t dst = ((size_t)z * Ss + sI) * Dd + d;
                    __nv_bfloat16 h0 = __float2bfloat16(v0);
                    __nv_bfloat16 h1 = __float2bfloat16(v1);
                    if (m == 0) { g_Khi[dst] = h0; g_Khi[dst + 1] = h1; }
                    else        { g_Qhi[dst] = h0; g_Qhi[dst + 1] = h1; }
                }
            }
}

// ---------------- scores = Q K^T * SCALE, compact lower-triangle grid, 1-pass bf16 ----
// blockIdx.x = t in [0,136) -> (by, bx) with bx <= by
__global__ __launch_bounds__(256, 2) void mma_scores() {
    extern __shared__ __align__(16) char smd[];
    int t = blockIdx.x;
    int by = (int)((sqrtf(8.0f * t + 1.0f) - 1.0f) * 0.5f);
    while ((by + 1) * (by + 2) / 2 <= t) by++;
    while (by * (by + 1) / 2 > t) by--;
    int bx = t - by * (by + 1) / 2;

    int tid = threadIdx.x, lane = tid & 31, w = tid >> 5;
    int wm = (w & 1) * 64, wn = (w >> 1) * 32;
    uint32_t sbase = smem_u32(smd);
    int z = blockIdx.z;
    int rowBase = by * 128, colBase = bx * 128;
    size_t qo = (size_t)z * Ss * Dd;
    const __nv_bfloat16* Qh = g_Qhi + qo + (size_t)rowBase * Dd;
    const __nv_bfloat16* Kh = g_Khi + qo + (size_t)colBase * Dd;
    float acc[4][4][4] = {};
    Seg seg[3] = { { Qh, Kh, Dd }, { Qh, Kh, 0 }, { Qh, Kh, 0 } };
    gemm_run(seg, Dd, Dd, sbase, acc, wm, wn, lane);

    __nv_bfloat16* C = g_scores + (size_t)z * Ss * Ss;
    int lr = lane >> 2, lc = (lane & 3) * 2;
#pragma unroll
    for (int mi = 0; mi < 4; mi++)
#pragma unroll
        for (int ni = 0; ni < 4; ni++)
#pragma unroll
            for (int half = 0; half < 2; half++) {
                int gr = rowBase + wm + mi * 16 + lr + half * 8;
                int col = colBase + wn + ni * 8 + lc;
                __nv_bfloat16 b0 = __float2bfloat16(acc[mi][ni][half * 2] * SCALE);
                __nv_bfloat16 b1 = __float2bfloat16(acc[mi][ni][half * 2 + 1] * SCALE);
                uint32_t packed = (uint32_t)*(uint16_t*)&b0 | ((uint32_t)*(uint16_t*)&b1 << 16);
                *(uint32_t*)&C[(size_t)gr * Ss + col] = packed;
            }
}

// ---------------- causal softmax; bf16 logits in, heavy rows first, P up to Lpad ----------------
__global__ __launch_bounds__(256) void softmax_rows() {
    __shared__ float red[8];
    int gid = blockIdx.x;
    int z = gid >> 11;
    int i = 2047 - (gid & 2047);      // heavy rows scheduled first
    size_t ro = (size_t)z * Ss * Ss + (size_t)i * Ss;
    const __nv_bfloat16* row = g_scores + ro;
    int L = i + 1;
    int Lpad = ((i >> 7) + 1) << 7;   // = kEnd boundary that mma_pv consumes
    int tid = threadIdx.x;
    float v[8];
#pragma unroll
    for (int s = 0; s < 8; s++) {
        int j = tid + s * 256;
        v[s] = (j < L) ? __bfloat162float(row[j]) : -3.4e38f;
    }
    float mx = v[0];
#pragma unroll
    for (int s = 1; s < 8; s++) mx = fmaxf(mx, v[s]);
#pragma unroll
    for (int o = 16; o; o >>= 1) mx = fmaxf(mx, __shfl_xor_sync(0xffffffffu, mx, o));
    if ((tid & 31) == 0) red[tid >> 5] = mx;
    __syncthreads();
    mx = red[0];
#pragma unroll
    for (int ww = 1; ww < 8; ww++) mx = fmaxf(mx, red[ww]);
    __syncthreads();
    float e[8];
    float sum = 0.f;
#pragma unroll
    for (int s = 0; s < 8; s++) {
        int j = tid + s * 256;
        e[s] = (j < L) ? __expf(v[s] - mx) : 0.0f;
        sum += e[s];
    }
#pragma unroll
    for (int o = 16; o; o >>= 1) sum += __shfl_xor_sync(0xffffffffu, sum, o);
    if ((tid & 31) == 0) red[tid >> 5] = sum;
    __syncthreads();
    sum = red[0];
#pragma unroll
    for (int ww = 1; ww < 8; ww++) sum += red[ww];
    float inv = 1.0f / sum;
#pragma unroll
    for (int s = 0; s < 8; s++) {
        int j = tid + s * 256;
        if (j < Lpad) {
            float p = e[s] * inv;
            __nv_bfloat16 hi, lo;
            split2(p, hi, lo);
            g_Phi[ro + j] = hi;
            g_Plo[ro + j] = lo;
        }
    }
}

// ---------------- Z = P V (causal K-limit) -> concat hi/lo; heavy tiles first ----------------
__global__ __launch_bounds__(256, 2) void mma_pv() {
    extern __shared__ __align__(16) char smd[];
    int tid = threadIdx.x, lane = tid & 31, w = tid >> 5;
    int wm = (w & 1) * 64, wn = (w >> 1) * 32;
    uint32_t sbase = smem_u32(smd);
    int z = blockIdx.z;
    int by = 15 - blockIdx.y;          // heavy-first
    int rowBase = by * 128, colBase = blockIdx.x * 128;
    int kEnd = rowBase + 128;
    const __nv_bfloat16* Ph = g_Phi + (size_t)z * Ss * Ss + (size_t)rowBase * Ss;
    const __nv_bfloat16* Pl = g_Plo + (size_t)z * Ss * Ss + (size_t)rowBase * Ss;
    const __nv_bfloat16* Vh = g_Vthi + (size_t)z * Dd * Ss + (size_t)colBase * Ss;
    const __nv_bfloat16* Vl = g_Vtlo + (size_t)z * Dd * Ss + (size_t)colBase * Ss;
    float acc[4][4][4] = {};
    Seg seg[3] = { { Ph, Vh, kEnd }, { Pl, Vh, kEnd }, { Ph, Vl, kEnd } };
    gemm_run(seg, Ss, Ss, sbase, acc, wm, wn, lane);

    int b = z / Hh, h = z % Hh;
    int lr = lane >> 2, lc = (lane & 3) * 2;
#pragma unroll
    for (int mi = 0; mi < 4; mi++)
#pragma unroll
        for (int ni = 0; ni < 4; ni++)
#pragma unroll
            for (int half = 0; half < 2; half++) {
                int sI = rowBase + wm + mi * 16 + lr + half * 8;
                int d = colBase + wn + ni * 8 + lc;
                __nv_bfloat16 h0, l0, h1, l1;
                split2(acc[mi][ni][half * 2], h0, l0);
                split2(acc[mi][ni][half * 2 + 1], h1, l1);
                size_t dst = ((size_t)(b * Ss + sI)) * Ee + h * Dd + d;
                g_Chi[dst] = h0; g_Clo[dst] = l0;
                g_Chi[dst + 1] = h1; g_Clo[dst + 1] = l1;
            }
}

// ---------------- out = concat @ Wo + bo ----------------
__global__ __launch_bounds__(256, 2) void mma_out(const float* __restrict__ bo,
                                                  float* __restrict__ out) {
    extern __shared__ __align__(16) char smd[];
    int tid = threadIdx.x, lane = tid & 31, w = tid >> 5;
    int wm = (w & 1) * 64, wn = (w >> 1) * 32;
    uint32_t sbase = smem_u32(smd);
    int rowBase = blockIdx.y * 128, colBase = blockIdx.x * 128;
    float acc[4][4][4] = {};
    Seg seg[3] = {
        { g_Chi + (size_t)rowBase * Ee, g_Wohi + (size_t)colBase * Ee, Ee },
        { g_Clo + (size_t)rowBase * Ee, g_Wohi + (size_t)colBase * Ee, Ee },
        { g_Chi + (size_t)rowBase * Ee, g_Wolo + (size_t)colBase * Ee, Ee } };
    gemm_run(seg, Ee, Ee, sbase, acc, wm, wn, lane);

    int lr = lane >> 2, lc = (lane & 3) * 2;
#pragma unroll
    for (int mi = 0; mi < 4; mi++)
#pragma unroll
        for (int ni = 0; ni < 4; ni++)
#pragma unroll
            for (int half = 0; half < 2; half++) {
                int gr = rowBase + wm + mi * 16 + lr + half * 8;
                int col = colBase + wn + ni * 8 + lc;
                float2 v = make_float2(acc[mi][ni][half * 2] + bo[col],
                                       acc[mi][ni][half * 2 + 1] + bo[col + 1]);
                *(float2*)&out[(size_t)gr * Ee + col] = v;
            }
}

// ---------------- launch ----------------
extern "C" void kernel_launch(void* const* d_in, const int* in_sizes, int n_in,
                              void* d_out, int out_size) {
    const float* Xk = (const float*)d_in[0];
    const float* Xv = (const float*)d_in[1];
    const float* Xq = (const float*)d_in[2];
    const float* WK = (const float*)d_in[3];
    const float* WV = (const float*)d_in[4];
    const float* WQ = (const float*)d_in[5];
    const float* Wo = (const float*)d_in[6];
    const float* bo = (const float*)d_in[7];
    float* out = (float*)d_out;

    // opt-in to >48KB dynamic smem (host-side attribute set; idempotent)
    cudaFuncSetAttribute(mma_proj, cudaFuncAttributeMaxDynamicSharedMemorySize, SMEM_TOTAL);
    cudaFuncSetAttribute(mma_scores, cudaFuncAttributeMaxDynamicSharedMemorySize, SMEM_TOTAL);
    cudaFuncSetAttribute(mma_pv, cudaFuncAttributeMaxDynamicSharedMemorySize, SMEM_TOTAL);
    cudaFuncSetAttribute(mma_out, cudaFuncAttributeMaxDynamicSharedMemorySize, SMEM_TOTAL);

    conv_inputs<<<(NE + 255) / 256, 256>>>(Xk, Xv, Xq);
    conv_weights<<<(EE + 255) / 256, 256>>>(WK, WV, WQ, Wo);

    dim3 gProj(Ee / 128, (Bb * Ss) / 128, 3);  // (6, 64, 3) — V first (heavy), then K, Q
    mma_proj<<<gProj, 256, SMEM_TOTAL>>>();

    dim3 gSc(136, 1, BHh);                     // compact lower triangle: 136 tiles x 12
    mma_scores<<<gSc, 256, SMEM_TOTAL>>>();

    softmax_rows<<<BHh * Ss, 256>>>();

    dim3 gPv(Dd / 128, Ss / 128, BHh);         // (2, 16, 12), heavy-first row mapping
    mma_pv<<<gPv, 256, SMEM_TOTAL>>>();

    dim3 gOut(Ee / 128, (Bb * Ss) / 128);      // (6, 64)
    mma_out<<<gOut, 256, SMEM_TOTAL>>>(bo, out);
}